// round 11
// baseline (speedup 1.0000x reference)
#include <cuda_runtime.h>

// FAC 3x3 dynamic filtering + LeakyReLU(0.2)
// feature: [N=8, C=64, H=128, W=128] f32
// filters: [N, C*9, H, W] f32, channel index = c*9 + t, tap t = kh*3 + kw (row-major)
// out[n,c,h,w] = sum_{kh,kw} feat_zeropad[n,c,h+kh-1,w+kw-1] * filt[n,c*9+kh*3+kw,h,w]
// then leaky relu slope 0.2.
//
// Mapping: one warp = TWO consecutive output rows (h0, h0+1) of one (n,c)
// plane. 32 lanes x 4 px = 128 = W. 22 vector loads per thread (18 filter
// taps + 4 shared feature rows) are front-batched for maximum MLP. Halo
// pixels via warp shuffles; all control flow warp-uniform.

#define N_ 8
#define C_ 64
#define H_ 128
#define W_ 128
#define HW_ (H_ * W_)

__device__ __forceinline__ float4 fac_row(
    float4 a, float la, float ra,     // feature row above (kh=0)
    float4 b, float lb, float rb,     // center row       (kh=1)
    float4 c, float lc, float rc,     // row below        (kh=2)
    float4 f0, float4 f1, float4 f2,
    float4 f3, float4 f4, float4 f5,
    float4 f6, float4 f7, float4 f8)
{
    float4 acc;
    acc.x =          la  * f0.x;
    acc.y =          a.x * f0.y;
    acc.z =          a.y * f0.z;
    acc.w =          a.z * f0.w;
    acc.x = fmaf(a.x, f1.x, acc.x);
    acc.y = fmaf(a.y, f1.y, acc.y);
    acc.z = fmaf(a.z, f1.z, acc.z);
    acc.w = fmaf(a.w, f1.w, acc.w);
    acc.x = fmaf(a.y, f2.x, acc.x);
    acc.y = fmaf(a.z, f2.y, acc.y);
    acc.z = fmaf(a.w, f2.z, acc.z);
    acc.w = fmaf(ra,  f2.w, acc.w);

    acc.x = fmaf(lb,  f3.x, acc.x);
    acc.y = fmaf(b.x, f3.y, acc.y);
    acc.z = fmaf(b.y, f3.z, acc.z);
    acc.w = fmaf(b.z, f3.w, acc.w);
    acc.x = fmaf(b.x, f4.x, acc.x);
    acc.y = fmaf(b.y, f4.y, acc.y);
    acc.z = fmaf(b.z, f4.z, acc.z);
    acc.w = fmaf(b.w, f4.w, acc.w);
    acc.x = fmaf(b.y, f5.x, acc.x);
    acc.y = fmaf(b.z, f5.y, acc.y);
    acc.z = fmaf(b.w, f5.z, acc.z);
    acc.w = fmaf(rb,  f5.w, acc.w);

    acc.x = fmaf(lc,  f6.x, acc.x);
    acc.y = fmaf(c.x, f6.y, acc.y);
    acc.z = fmaf(c.y, f6.z, acc.z);
    acc.w = fmaf(c.z, f6.w, acc.w);
    acc.x = fmaf(c.x, f7.x, acc.x);
    acc.y = fmaf(c.y, f7.y, acc.y);
    acc.z = fmaf(c.z, f7.z, acc.z);
    acc.w = fmaf(c.w, f7.w, acc.w);
    acc.x = fmaf(c.y, f8.x, acc.x);
    acc.y = fmaf(c.z, f8.y, acc.y);
    acc.z = fmaf(c.w, f8.z, acc.z);
    acc.w = fmaf(rc,  f8.w, acc.w);
    return acc;
}

__device__ __forceinline__ float4 leaky4(float4 v)
{
    v.x = (v.x >= 0.f) ? v.x : 0.2f * v.x;
    v.y = (v.y >= 0.f) ? v.y : 0.2f * v.y;
    v.z = (v.z >= 0.f) ? v.z : 0.2f * v.z;
    v.w = (v.w >= 0.f) ? v.w : 0.2f * v.w;
    return v;
}

__global__ __launch_bounds__(256) void fac_leaky_kernel(
    const float* __restrict__ feat,
    const float* __restrict__ filt,
    float* __restrict__ out)
{
    int idx  = blockIdx.x * blockDim.x + threadIdx.x;
    int lane = idx & 31;
    int wrp  = idx >> 5;           // 32768 warps
    int hp   = wrp & 63;           // row-pair index
    int nc   = wrp >> 6;           // 0..511
    int h0   = hp << 1;            // even row
    int h1   = h0 + 1;
    int w    = lane << 2;

    const float*  fplane = feat + nc * HW_ + w;
    const float4* fb0 = reinterpret_cast<const float4*>(
        filt + (size_t)nc * 9 * HW_ + h0 * W_ + w);
    const float4* fb1 = fb0 + (W_ / 4);          // next row, same taps
    const float4 z4 = make_float4(0.f, 0.f, 0.f, 0.f);

    // ---- front-batched loads: 18 filter vectors (9 taps x 2 rows) ----
    float4 a0 = __ldcs(fb0 + 0 * (HW_ / 4));
    float4 a1 = __ldcs(fb0 + 1 * (HW_ / 4));
    float4 a2 = __ldcs(fb0 + 2 * (HW_ / 4));
    float4 a3 = __ldcs(fb0 + 3 * (HW_ / 4));
    float4 a4 = __ldcs(fb0 + 4 * (HW_ / 4));
    float4 a5 = __ldcs(fb0 + 5 * (HW_ / 4));
    float4 a6 = __ldcs(fb0 + 6 * (HW_ / 4));
    float4 a7 = __ldcs(fb0 + 7 * (HW_ / 4));
    float4 a8 = __ldcs(fb0 + 8 * (HW_ / 4));
    float4 b0 = __ldcs(fb1 + 0 * (HW_ / 4));
    float4 b1 = __ldcs(fb1 + 1 * (HW_ / 4));
    float4 b2 = __ldcs(fb1 + 2 * (HW_ / 4));
    float4 b3 = __ldcs(fb1 + 3 * (HW_ / 4));
    float4 b4 = __ldcs(fb1 + 4 * (HW_ / 4));
    float4 b5 = __ldcs(fb1 + 5 * (HW_ / 4));
    float4 b6 = __ldcs(fb1 + 6 * (HW_ / 4));
    float4 b7 = __ldcs(fb1 + 7 * (HW_ / 4));
    float4 b8 = __ldcs(fb1 + 8 * (HW_ / 4));

    // ---- 4 shared feature rows: h0-1, h0, h1, h1+1 ----
    float4 m0 = (h0 > 0)       ? __ldg(reinterpret_cast<const float4*>(fplane + (h0 - 1) * W_)) : z4;
    float4 m1 =                  __ldg(reinterpret_cast<const float4*>(fplane +  h0      * W_));
    float4 m2 =                  __ldg(reinterpret_cast<const float4*>(fplane +  h1      * W_));
    float4 m3 = (h1 < H_ - 1)  ? __ldg(reinterpret_cast<const float4*>(fplane + (h1 + 1) * W_)) : z4;

    // ---- halos via shuffles ----
    float l0 = __shfl_up_sync(0xFFFFFFFFu, m0.w, 1);
    float l1 = __shfl_up_sync(0xFFFFFFFFu, m1.w, 1);
    float l2 = __shfl_up_sync(0xFFFFFFFFu, m2.w, 1);
    float l3 = __shfl_up_sync(0xFFFFFFFFu, m3.w, 1);
    float r0 = __shfl_down_sync(0xFFFFFFFFu, m0.x, 1);
    float r1 = __shfl_down_sync(0xFFFFFFFFu, m1.x, 1);
    float r2 = __shfl_down_sync(0xFFFFFFFFu, m2.x, 1);
    float r3 = __shfl_down_sync(0xFFFFFFFFu, m3.x, 1);
    if (lane == 0)  { l0 = 0.f; l1 = 0.f; l2 = 0.f; l3 = 0.f; }
    if (lane == 31) { r0 = 0.f; r1 = 0.f; r2 = 0.f; r3 = 0.f; }

    // ---- compute both rows ----
    float4 o0 = fac_row(m0, l0, r0,  m1, l1, r1,  m2, l2, r2,
                        a0, a1, a2, a3, a4, a5, a6, a7, a8);
    float4 o1 = fac_row(m1, l1, r1,  m2, l2, r2,  m3, l3, r3,
                        b0, b1, b2, b3, b4, b5, b6, b7, b8);

    float* obase = out + nc * HW_ + h0 * W_ + w;
    __stcs(reinterpret_cast<float4*>(obase),       leaky4(o0));
    __stcs(reinterpret_cast<float4*>(obase + W_),  leaky4(o1));
}

extern "C" void kernel_launch(void* const* d_in, const int* in_sizes, int n_in,
                              void* d_out, int out_size)
{
    const float* feat = (const float*)d_in[0];   // [8,64,128,128]
    const float* filt = (const float*)d_in[1];   // [8,576,128,128]
    float* out = (float*)d_out;                  // [8,64,128,128]

    // 32768 warps -> 1,048,576 threads -> 4096 blocks of 256
    fac_leaky_kernel<<<4096, 256>>>(feat, filt, out);
}

// round 12
// speedup vs baseline: 1.0448x; 1.0448x over previous
#include <cuda_runtime.h>

// FAC 3x3 dynamic filtering + LeakyReLU(0.2)
// feature: [N=8, C=64, H=128, W=128] f32
// filters: [N, C*9, H, W] f32, channel index = c*9 + t, tap t = kh*3 + kw (row-major)
// out[n,c,h,w] = sum_{kh,kw} feat_zeropad[n,c,h+kh-1,w+kw-1] * filt[n,c*9+kh*3+kw,h,w]
// then leaky relu slope 0.2.
//
// Mapping: one warp = one (n,c,h) row (32 lanes x 4 px = 128 = W).
// __launch_bounds__(256, 4) grants ptxas a 64-register budget so the 12
// front-batched vector loads (9 filter taps + 3 feature rows) stay live
// simultaneously -> MLP_eff ~12 per thread. Halo via warp shuffles;
// all control flow warp-uniform.

#define N_ 8
#define C_ 64
#define H_ 128
#define W_ 128
#define HW_ (H_ * W_)

__global__ __launch_bounds__(256, 4) void fac_leaky_kernel(
    const float* __restrict__ feat,
    const float* __restrict__ filt,
    float* __restrict__ out)
{
    int idx  = blockIdx.x * blockDim.x + threadIdx.x;
    int lane = idx & 31;
    int wrp  = idx >> 5;          // 65536 warps total
    int h    = wrp & 127;
    int nc   = wrp >> 7;          // 0..511
    int w    = lane << 2;

    const float*  fplane  = feat + nc * HW_ + w;
    const float4* filbase = reinterpret_cast<const float4*>(
        filt + (size_t)nc * 9 * HW_ + h * W_ + w);
    const float4 z4 = make_float4(0.f, 0.f, 0.f, 0.f);

    // ---- front-batched loads: 9 filter vectors (streaming, no reuse) ----
    float4 f0 = __ldcs(filbase + 0 * (HW_ / 4));
    float4 f1 = __ldcs(filbase + 1 * (HW_ / 4));
    float4 f2 = __ldcs(filbase + 2 * (HW_ / 4));
    float4 f3 = __ldcs(filbase + 3 * (HW_ / 4));
    float4 f4 = __ldcs(filbase + 4 * (HW_ / 4));
    float4 f5 = __ldcs(filbase + 5 * (HW_ / 4));
    float4 f6 = __ldcs(filbase + 6 * (HW_ / 4));
    float4 f7 = __ldcs(filbase + 7 * (HW_ / 4));
    float4 f8 = __ldcs(filbase + 8 * (HW_ / 4));

    // ---- front-batched loads: 3 feature rows (zero rows at v-boundary) ----
    float4 m0 = (h > 0)       ? __ldg(reinterpret_cast<const float4*>(fplane + (h - 1) * W_)) : z4;
    float4 m1 =                 __ldg(reinterpret_cast<const float4*>(fplane +  h      * W_));
    float4 m2 = (h < H_ - 1)  ? __ldg(reinterpret_cast<const float4*>(fplane + (h + 1) * W_)) : z4;

    // ---- halo via shuffles (cols w-1 and w+4 per row) ----
    float l0 = __shfl_up_sync(0xFFFFFFFFu, m0.w, 1);
    float l1 = __shfl_up_sync(0xFFFFFFFFu, m1.w, 1);
    float l2 = __shfl_up_sync(0xFFFFFFFFu, m2.w, 1);
    float r0 = __shfl_down_sync(0xFFFFFFFFu, m0.x, 1);
    float r1 = __shfl_down_sync(0xFFFFFFFFu, m1.x, 1);
    float r2 = __shfl_down_sync(0xFFFFFFFFu, m2.x, 1);
    if (lane == 0)  { l0 = 0.f; l1 = 0.f; l2 = 0.f; }
    if (lane == 31) { r0 = 0.f; r1 = 0.f; r2 = 0.f; }

    // ---- compute: acc[p] = sum_t e[row(t)][p + kw(t)] * f[t][p] ----
    float4 acc;
    // row above (kh=0): taps f0,f1,f2
    acc.x =          l0   * f0.x;
    acc.y =          m0.x * f0.y;
    acc.z =          m0.y * f0.z;
    acc.w =          m0.z * f0.w;
    acc.x = fmaf(m0.x, f1.x, acc.x);
    acc.y = fmaf(m0.y, f1.y, acc.y);
    acc.z = fmaf(m0.z, f1.z, acc.z);
    acc.w = fmaf(m0.w, f1.w, acc.w);
    acc.x = fmaf(m0.y, f2.x, acc.x);
    acc.y = fmaf(m0.z, f2.y, acc.y);
    acc.z = fmaf(m0.w, f2.z, acc.z);
    acc.w = fmaf(r0,   f2.w, acc.w);
    // center row (kh=1): taps f3,f4,f5
    acc.x = fmaf(l1,   f3.x, acc.x);
    acc.y = fmaf(m1.x, f3.y, acc.y);
    acc.z = fmaf(m1.y, f3.z, acc.z);
    acc.w = fmaf(m1.z, f3.w, acc.w);
    acc.x = fmaf(m1.x, f4.x, acc.x);
    acc.y = fmaf(m1.y, f4.y, acc.y);
    acc.z = fmaf(m1.z, f4.z, acc.z);
    acc.w = fmaf(m1.w, f4.w, acc.w);
    acc.x = fmaf(m1.y, f5.x, acc.x);
    acc.y = fmaf(m1.z, f5.y, acc.y);
    acc.z = fmaf(m1.w, f5.z, acc.z);
    acc.w = fmaf(r1,   f5.w, acc.w);
    // row below (kh=2): taps f6,f7,f8
    acc.x = fmaf(l2,   f6.x, acc.x);
    acc.y = fmaf(m2.x, f6.y, acc.y);
    acc.z = fmaf(m2.y, f6.z, acc.z);
    acc.w = fmaf(m2.z, f6.w, acc.w);
    acc.x = fmaf(m2.x, f7.x, acc.x);
    acc.y = fmaf(m2.y, f7.y, acc.y);
    acc.z = fmaf(m2.z, f7.z, acc.z);
    acc.w = fmaf(m2.w, f7.w, acc.w);
    acc.x = fmaf(m2.y, f8.x, acc.x);
    acc.y = fmaf(m2.z, f8.y, acc.y);
    acc.z = fmaf(m2.w, f8.z, acc.z);
    acc.w = fmaf(r2,   f8.w, acc.w);

    // LeakyReLU(0.2)
    acc.x = (acc.x >= 0.f) ? acc.x : 0.2f * acc.x;
    acc.y = (acc.y >= 0.f) ? acc.y : 0.2f * acc.y;
    acc.z = (acc.z >= 0.f) ? acc.z : 0.2f * acc.z;
    acc.w = (acc.w >= 0.f) ? acc.w : 0.2f * acc.w;

    __stcs(reinterpret_cast<float4*>(out + nc * HW_ + h * W_ + w), acc);
}

extern "C" void kernel_launch(void* const* d_in, const int* in_sizes, int n_in,
                              void* d_out, int out_size)
{
    const float* feat = (const float*)d_in[0];   // [8,64,128,128]
    const float* filt = (const float*)d_in[1];   // [8,576,128,128]
    float* out = (float*)d_out;                  // [8,64,128,128]

    fac_leaky_kernel<<<8192, 256>>>(feat, filt, out);
}

// round 13
// speedup vs baseline: 1.0497x; 1.0047x over previous
#include <cuda_runtime.h>

// FAC 3x3 dynamic filtering + LeakyReLU(0.2)
// feature: [N=8, C=64, H=128, W=128] f32
// filters: [N, C*9, H, W] f32, channel index = c*9 + t, tap t = kh*3 + kw (row-major)
// out[n,c,h,w] = sum_{kh,kw} feat_zeropad[n,c,h+kh-1,w+kw-1] * filt[n,c*9+kh*3+kw,h,w]
// then leaky relu slope 0.2.
//
// Mapping: one warp = one (n,c,h) row (32 lanes x 4 px = 128 = W).
// __launch_bounds__(256, 4) grants ptxas a 64-register budget so the 12
// front-batched vector loads (9 filter taps + 3 feature rows) stay live
// simultaneously -> MLP_eff ~12 per thread. Halo via warp shuffles;
// all control flow warp-uniform.

#define N_ 8
#define C_ 64
#define H_ 128
#define W_ 128
#define HW_ (H_ * W_)

__global__ __launch_bounds__(256, 4) void fac_leaky_kernel(
    const float* __restrict__ feat,
    const float* __restrict__ filt,
    float* __restrict__ out)
{
    int idx  = blockIdx.x * blockDim.x + threadIdx.x;
    int lane = idx & 31;
    int wrp  = idx >> 5;          // 65536 warps total
    int h    = wrp & 127;
    int nc   = wrp >> 7;          // 0..511
    int w    = lane << 2;

    const float*  fplane  = feat + nc * HW_ + w;
    const float4* filbase = reinterpret_cast<const float4*>(
        filt + (size_t)nc * 9 * HW_ + h * W_ + w);
    const float4 z4 = make_float4(0.f, 0.f, 0.f, 0.f);

    // ---- front-batched loads: 9 filter vectors (streaming, no reuse) ----
    float4 f0 = __ldcs(filbase + 0 * (HW_ / 4));
    float4 f1 = __ldcs(filbase + 1 * (HW_ / 4));
    float4 f2 = __ldcs(filbase + 2 * (HW_ / 4));
    float4 f3 = __ldcs(filbase + 3 * (HW_ / 4));
    float4 f4 = __ldcs(filbase + 4 * (HW_ / 4));
    float4 f5 = __ldcs(filbase + 5 * (HW_ / 4));
    float4 f6 = __ldcs(filbase + 6 * (HW_ / 4));
    float4 f7 = __ldcs(filbase + 7 * (HW_ / 4));
    float4 f8 = __ldcs(filbase + 8 * (HW_ / 4));

    // ---- front-batched loads: 3 feature rows (zero rows at v-boundary) ----
    float4 m0 = (h > 0)       ? __ldg(reinterpret_cast<const float4*>(fplane + (h - 1) * W_)) : z4;
    float4 m1 =                 __ldg(reinterpret_cast<const float4*>(fplane +  h      * W_));
    float4 m2 = (h < H_ - 1)  ? __ldg(reinterpret_cast<const float4*>(fplane + (h + 1) * W_)) : z4;

    // ---- halo via shuffles (cols w-1 and w+4 per row) ----
    float l0 = __shfl_up_sync(0xFFFFFFFFu, m0.w, 1);
    float l1 = __shfl_up_sync(0xFFFFFFFFu, m1.w, 1);
    float l2 = __shfl_up_sync(0xFFFFFFFFu, m2.w, 1);
    float r0 = __shfl_down_sync(0xFFFFFFFFu, m0.x, 1);
    float r1 = __shfl_down_sync(0xFFFFFFFFu, m1.x, 1);
    float r2 = __shfl_down_sync(0xFFFFFFFFu, m2.x, 1);
    if (lane == 0)  { l0 = 0.f; l1 = 0.f; l2 = 0.f; }
    if (lane == 31) { r0 = 0.f; r1 = 0.f; r2 = 0.f; }

    // ---- compute: acc[p] = sum_t e[row(t)][p + kw(t)] * f[t][p] ----
    float4 acc;
    // row above (kh=0): taps f0,f1,f2
    acc.x =          l0   * f0.x;
    acc.y =          m0.x * f0.y;
    acc.z =          m0.y * f0.z;
    acc.w =          m0.z * f0.w;
    acc.x = fmaf(m0.x, f1.x, acc.x);
    acc.y = fmaf(m0.y, f1.y, acc.y);
    acc.z = fmaf(m0.z, f1.z, acc.z);
    acc.w = fmaf(m0.w, f1.w, acc.w);
    acc.x = fmaf(m0.y, f2.x, acc.x);
    acc.y = fmaf(m0.z, f2.y, acc.y);
    acc.z = fmaf(m0.w, f2.z, acc.z);
    acc.w = fmaf(r0,   f2.w, acc.w);
    // center row (kh=1): taps f3,f4,f5
    acc.x = fmaf(l1,   f3.x, acc.x);
    acc.y = fmaf(m1.x, f3.y, acc.y);
    acc.z = fmaf(m1.y, f3.z, acc.z);
    acc.w = fmaf(m1.z, f3.w, acc.w);
    acc.x = fmaf(m1.x, f4.x, acc.x);
    acc.y = fmaf(m1.y, f4.y, acc.y);
    acc.z = fmaf(m1.z, f4.z, acc.z);
    acc.w = fmaf(m1.w, f4.w, acc.w);
    acc.x = fmaf(m1.y, f5.x, acc.x);
    acc.y = fmaf(m1.z, f5.y, acc.y);
    acc.z = fmaf(m1.w, f5.z, acc.z);
    acc.w = fmaf(r1,   f5.w, acc.w);
    // row below (kh=2): taps f6,f7,f8
    acc.x = fmaf(l2,   f6.x, acc.x);
    acc.y = fmaf(m2.x, f6.y, acc.y);
    acc.z = fmaf(m2.y, f6.z, acc.z);
    acc.w = fmaf(m2.z, f6.w, acc.w);
    acc.x = fmaf(m2.x, f7.x, acc.x);
    acc.y = fmaf(m2.y, f7.y, acc.y);
    acc.z = fmaf(m2.z, f7.z, acc.z);
    acc.w = fmaf(m2.w, f7.w, acc.w);
    acc.x = fmaf(m2.y, f8.x, acc.x);
    acc.y = fmaf(m2.z, f8.y, acc.y);
    acc.z = fmaf(m2.w, f8.z, acc.z);
    acc.w = fmaf(r2,   f8.w, acc.w);

    // LeakyReLU(0.2)
    acc.x = (acc.x >= 0.f) ? acc.x : 0.2f * acc.x;
    acc.y = (acc.y >= 0.f) ? acc.y : 0.2f * acc.y;
    acc.z = (acc.z >= 0.f) ? acc.z : 0.2f * acc.z;
    acc.w = (acc.w >= 0.f) ? acc.w : 0.2f * acc.w;

    __stcs(reinterpret_cast<float4*>(out + nc * HW_ + h * W_ + w), acc);
}

extern "C" void kernel_launch(void* const* d_in, const int* in_sizes, int n_in,
                              void* d_out, int out_size)
{
    const float* feat = (const float*)d_in[0];   // [8,64,128,128]
    const float* filt = (const float*)d_in[1];   // [8,576,128,128]
    float* out = (float*)d_out;                  // [8,64,128,128]

    fac_leaky_kernel<<<8192, 256>>>(feat, filt, out);
}

// round 14
// speedup vs baseline: 1.0547x; 1.0047x over previous
#include <cuda_runtime.h>

// FAC 3x3 dynamic filtering + LeakyReLU(0.2)
// feature: [N=8, C=64, H=128, W=128] f32
// filters: [N, C*9, H, W] f32, channel index = c*9 + t, tap t = kh*3 + kw (row-major)
// out[n,c,h,w] = sum_{kh,kw} feat_zeropad[n,c,h+kh-1,w+kw-1] * filt[n,c*9+kh*3+kw,h,w]
// then leaky relu slope 0.2.
//
// Mapping: one warp = one (n,c,h) row (32 lanes x 4 px = 128 = W).
// __launch_bounds__(256, 4) grants ptxas a 64-register budget so the 12
// front-batched vector loads (9 filter taps + 3 feature rows) stay live
// simultaneously -> MLP_eff ~12 per thread. Halo via warp shuffles;
// all control flow warp-uniform.

#define N_ 8
#define C_ 64
#define H_ 128
#define W_ 128
#define HW_ (H_ * W_)

__global__ __launch_bounds__(256, 4) void fac_leaky_kernel(
    const float* __restrict__ feat,
    const float* __restrict__ filt,
    float* __restrict__ out)
{
    int idx  = blockIdx.x * blockDim.x + threadIdx.x;
    int lane = idx & 31;
    int wrp  = idx >> 5;          // 65536 warps total
    int h    = wrp & 127;
    int nc   = wrp >> 7;          // 0..511
    int w    = lane << 2;

    const float*  fplane  = feat + nc * HW_ + w;
    const float4* filbase = reinterpret_cast<const float4*>(
        filt + (size_t)nc * 9 * HW_ + h * W_ + w);
    const float4 z4 = make_float4(0.f, 0.f, 0.f, 0.f);

    // ---- front-batched loads: 9 filter vectors (streaming, no reuse) ----
    float4 f0 = __ldcs(filbase + 0 * (HW_ / 4));
    float4 f1 = __ldcs(filbase + 1 * (HW_ / 4));
    float4 f2 = __ldcs(filbase + 2 * (HW_ / 4));
    float4 f3 = __ldcs(filbase + 3 * (HW_ / 4));
    float4 f4 = __ldcs(filbase + 4 * (HW_ / 4));
    float4 f5 = __ldcs(filbase + 5 * (HW_ / 4));
    float4 f6 = __ldcs(filbase + 6 * (HW_ / 4));
    float4 f7 = __ldcs(filbase + 7 * (HW_ / 4));
    float4 f8 = __ldcs(filbase + 8 * (HW_ / 4));

    // ---- front-batched loads: 3 feature rows (zero rows at v-boundary) ----
    float4 m0 = (h > 0)       ? __ldg(reinterpret_cast<const float4*>(fplane + (h - 1) * W_)) : z4;
    float4 m1 =                 __ldg(reinterpret_cast<const float4*>(fplane +  h      * W_));
    float4 m2 = (h < H_ - 1)  ? __ldg(reinterpret_cast<const float4*>(fplane + (h + 1) * W_)) : z4;

    // ---- halo via shuffles (cols w-1 and w+4 per row) ----
    float l0 = __shfl_up_sync(0xFFFFFFFFu, m0.w, 1);
    float l1 = __shfl_up_sync(0xFFFFFFFFu, m1.w, 1);
    float l2 = __shfl_up_sync(0xFFFFFFFFu, m2.w, 1);
    float r0 = __shfl_down_sync(0xFFFFFFFFu, m0.x, 1);
    float r1 = __shfl_down_sync(0xFFFFFFFFu, m1.x, 1);
    float r2 = __shfl_down_sync(0xFFFFFFFFu, m2.x, 1);
    if (lane == 0)  { l0 = 0.f; l1 = 0.f; l2 = 0.f; }
    if (lane == 31) { r0 = 0.f; r1 = 0.f; r2 = 0.f; }

    // ---- compute: acc[p] = sum_t e[row(t)][p + kw(t)] * f[t][p] ----
    float4 acc;
    // row above (kh=0): taps f0,f1,f2
    acc.x =          l0   * f0.x;
    acc.y =          m0.x * f0.y;
    acc.z =          m0.y * f0.z;
    acc.w =          m0.z * f0.w;
    acc.x = fmaf(m0.x, f1.x, acc.x);
    acc.y = fmaf(m0.y, f1.y, acc.y);
    acc.z = fmaf(m0.z, f1.z, acc.z);
    acc.w = fmaf(m0.w, f1.w, acc.w);
    acc.x = fmaf(m0.y, f2.x, acc.x);
    acc.y = fmaf(m0.z, f2.y, acc.y);
    acc.z = fmaf(m0.w, f2.z, acc.z);
    acc.w = fmaf(r0,   f2.w, acc.w);
    // center row (kh=1): taps f3,f4,f5
    acc.x = fmaf(l1,   f3.x, acc.x);
    acc.y = fmaf(m1.x, f3.y, acc.y);
    acc.z = fmaf(m1.y, f3.z, acc.z);
    acc.w = fmaf(m1.z, f3.w, acc.w);
    acc.x = fmaf(m1.x, f4.x, acc.x);
    acc.y = fmaf(m1.y, f4.y, acc.y);
    acc.z = fmaf(m1.z, f4.z, acc.z);
    acc.w = fmaf(m1.w, f4.w, acc.w);
    acc.x = fmaf(m1.y, f5.x, acc.x);
    acc.y = fmaf(m1.z, f5.y, acc.y);
    acc.z = fmaf(m1.w, f5.z, acc.z);
    acc.w = fmaf(r1,   f5.w, acc.w);
    // row below (kh=2): taps f6,f7,f8
    acc.x = fmaf(l2,   f6.x, acc.x);
    acc.y = fmaf(m2.x, f6.y, acc.y);
    acc.z = fmaf(m2.y, f6.z, acc.z);
    acc.w = fmaf(m2.z, f6.w, acc.w);
    acc.x = fmaf(m2.x, f7.x, acc.x);
    acc.y = fmaf(m2.y, f7.y, acc.y);
    acc.z = fmaf(m2.z, f7.z, acc.z);
    acc.w = fmaf(m2.w, f7.w, acc.w);
    acc.x = fmaf(m2.y, f8.x, acc.x);
    acc.y = fmaf(m2.z, f8.y, acc.y);
    acc.z = fmaf(m2.w, f8.z, acc.z);
    acc.w = fmaf(r2,   f8.w, acc.w);

    // LeakyReLU(0.2)
    acc.x = (acc.x >= 0.f) ? acc.x : 0.2f * acc.x;
    acc.y = (acc.y >= 0.f) ? acc.y : 0.2f * acc.y;
    acc.z = (acc.z >= 0.f) ? acc.z : 0.2f * acc.z;
    acc.w = (acc.w >= 0.f) ? acc.w : 0.2f * acc.w;

    __stcs(reinterpret_cast<float4*>(out + nc * HW_ + h * W_ + w), acc);
}

extern "C" void kernel_launch(void* const* d_in, const int* in_sizes, int n_in,
                              void* d_out, int out_size)
{
    const float* feat = (const float*)d_in[0];   // [8,64,128,128]
    const float* filt = (const float*)d_in[1];   // [8,576,128,128]
    float* out = (float*)d_out;                  // [8,64,128,128]

    fac_leaky_kernel<<<8192, 256>>>(feat, filt, out);
}